// round 3
// baseline (speedup 1.0000x reference)
#include <cuda_runtime.h>
#include <math.h>

#define BB 4
#define TT 2048
#define CC 1024
#define HH 16
#define HD 64
#define MM (BB*TT)          // 8192 rows
#define NQKV (3*CC)         // 3072

// Scratch (device globals; allocation-free per harness rules)
__device__ float g_qkv[(size_t)MM * NQKV];   // [B,T,3C]
__device__ float g_q[(size_t)MM * CC];       // [B,H,T,hd]
__device__ float g_k[(size_t)MM * CC];       // [B,H,T,hd]
__device__ float g_v[(size_t)MM * CC];       // [B,H,T,hd]
__device__ float g_att[(size_t)MM * CC];     // [B,T,C]

// ---------------------------------------------------------------------------
// SGEMM: C[M,N] = A[M,K] @ B[K,N] + bias[N]   (row-major, all dims multiples)
// BM=BN=128, BK=16, 256 threads, 8x8 per thread.
// ---------------------------------------------------------------------------
__global__ __launch_bounds__(256) void sgemm_bias_kernel(
    const float* __restrict__ A, const float* __restrict__ B,
    const float* __restrict__ bias, float* __restrict__ C,
    int Nd, int Kd)
{
    const int BM = 128, BN = 128, BK = 16;
    __shared__ float As[BK][BM];
    __shared__ float Bs[BK][BN];

    int tid = threadIdx.x;
    int bm = blockIdx.y * BM;
    int bn = blockIdx.x * BN;
    int tr = tid >> 4;        // 0..15
    int tc = tid & 15;        // 0..15

    float acc[8][8];
#pragma unroll
    for (int i = 0; i < 8; i++)
#pragma unroll
        for (int j = 0; j < 8; j++) acc[i][j] = 0.f;

    for (int k0 = 0; k0 < Kd; k0 += BK) {
        // Load A tile (BMxBK) transposed into As, B tile (BKxBN) into Bs.
#pragma unroll
        for (int it = 0; it < 2; it++) {
            int idx = tid + it * 256;            // 0..511 float4 slots
            // A: slot -> (m, kq4)
            int m  = idx >> 2;
            int kq = (idx & 3) << 2;
            float4 a4 = *(const float4*)&A[(size_t)(bm + m) * Kd + k0 + kq];
            As[kq + 0][m] = a4.x;
            As[kq + 1][m] = a4.y;
            As[kq + 2][m] = a4.z;
            As[kq + 3][m] = a4.w;
            // B: slot -> (k, nv4)
            int k  = idx >> 5;
            int nv = (idx & 31) << 2;
            *(float4*)&Bs[k][nv] = *(const float4*)&B[(size_t)(k0 + k) * Nd + bn + nv];
        }
        __syncthreads();

#pragma unroll
        for (int kk = 0; kk < BK; kk++) {
            float a[8], b[8];
            *(float4*)&a[0] = *(float4*)&As[kk][tr * 8];
            *(float4*)&a[4] = *(float4*)&As[kk][tr * 8 + 4];
            *(float4*)&b[0] = *(float4*)&Bs[kk][tc * 8];
            *(float4*)&b[4] = *(float4*)&Bs[kk][tc * 8 + 4];
#pragma unroll
            for (int i = 0; i < 8; i++)
#pragma unroll
                for (int j = 0; j < 8; j++)
                    acc[i][j] += a[i] * b[j];
        }
        __syncthreads();
    }

    float bj[8];
#pragma unroll
    for (int j = 0; j < 8; j++) bj[j] = bias[bn + tc * 8 + j];

#pragma unroll
    for (int i = 0; i < 8; i++) {
        size_t row = (size_t)(bm + tr * 8 + i) * Nd + bn + tc * 8;
        float4 o0, o1;
        o0.x = acc[i][0] + bj[0]; o0.y = acc[i][1] + bj[1];
        o0.z = acc[i][2] + bj[2]; o0.w = acc[i][3] + bj[3];
        o1.x = acc[i][4] + bj[4]; o1.y = acc[i][5] + bj[5];
        o1.z = acc[i][6] + bj[6]; o1.w = acc[i][7] + bj[7];
        *(float4*)&C[row]     = o0;
        *(float4*)&C[row + 4] = o1;
    }
}

// ---------------------------------------------------------------------------
// RoPE + split qkv into head-major Q/K/V layouts [B,H,T,hd].
// One thread per (b,h,t,d) with d in [0,32): handles rotation pair (d, d+32).
// ---------------------------------------------------------------------------
__global__ __launch_bounds__(256) void rope_split_kernel()
{
    int idx = blockIdx.x * blockDim.x + threadIdx.x;
    // bits: d(5) | t(11) | h(4) | b(2)
    int d = idx & 31;
    int t = (idx >> 5) & (TT - 1);
    int h = (idx >> 16) & (HH - 1);
    int b = idx >> 20;

    const float* row = g_qkv + ((size_t)(b * TT + t)) * NQKV + h * HD + d;
    float q1 = row[0],        q2 = row[32];
    float k1 = row[CC],       k2 = row[CC + 32];
    float v1 = row[2 * CC],   v2 = row[2 * CC + 32];

    // inv_freq = 10000^(-d/32) = 2^(-d * log2(10000)/32)
    float inv = exp2f(-(float)d * 0.4152410118609203f);
    float ang = (float)t * inv;
    float s, c;
    sincosf(ang, &s, &c);

    size_t o = ((size_t)((b * HH + h) * TT + t)) * HD + d;
    g_q[o]      = q1 * c - q2 * s;
    g_q[o + 32] = q2 * c + q1 * s;
    g_k[o]      = k1 * c - k2 * s;
    g_k[o + 32] = k2 * c + k1 * s;
    g_v[o]      = v1;
    g_v[o + 32] = v2;
}

// ---------------------------------------------------------------------------
// Flash attention (fp32, causal). Block = one (b,h) x 64-row Q tile.
// 256 threads = 16x16; S cols interleaved (tc+16j) for conflict-free K reads,
// O cols contiguous (tc*4+j) for conflict-free V reads; P in smem bridges.
// ---------------------------------------------------------------------------
#define KPAD 68
#define ATTN_SMEM_BYTES ((64*64 + 3*64*KPAD) * 4)

__global__ __launch_bounds__(256) void flash_attn_kernel()
{
    extern __shared__ float sm[];
    float* sQ = sm;                       // [64][64]
    float* sK = sm + 64 * 64;             // [64][KPAD]
    float* sV = sK + 64 * KPAD;           // [64][KPAD]
    float* sP = sV + 64 * KPAD;           // [64][KPAD]

    int bh = blockIdx.y;
    int qt = (int)gridDim.x - 1 - (int)blockIdx.x;   // heavy tiles first
    int tid = threadIdx.x;
    int tr = tid >> 4;
    int tc = tid & 15;
    int r0 = tr * 4;

    const float* Qh = g_q + (size_t)bh * TT * HD;
    const float* Kh = g_k + (size_t)bh * TT * HD;
    const float* Vh = g_v + (size_t)bh * TT * HD;

    // Load Q tile
#pragma unroll
    for (int it = 0; it < 4; it++) {
        int i = tid + it * 256;           // float4 slot, 1024 total
        int r = i >> 4, dv = (i & 15) << 2;
        *(float4*)&sQ[r * 64 + dv] = *(const float4*)&Qh[(size_t)(qt * 64 + r) * HD + dv];
    }

    float m[4], l[4], acc[4][4];
#pragma unroll
    for (int i = 0; i < 4; i++) {
        m[i] = -1e30f; l[i] = 0.f;
#pragma unroll
        for (int j = 0; j < 4; j++) acc[i][j] = 0.f;
    }

    for (int kt = 0; kt <= qt; kt++) {
        __syncthreads();  // protect sK/sV/sP from previous iteration readers
        // Load K,V tiles
#pragma unroll
        for (int it = 0; it < 4; it++) {
            int i = tid + it * 256;
            int r = i >> 4, dv = (i & 15) << 2;
            *(float4*)&sK[r * KPAD + dv] = *(const float4*)&Kh[(size_t)(kt * 64 + r) * HD + dv];
            *(float4*)&sV[r * KPAD + dv] = *(const float4*)&Vh[(size_t)(kt * 64 + r) * HD + dv];
        }
        __syncthreads();

        // S = Q K^T : rows r0..r0+3, cols tc+16j
        float s[4][4];
#pragma unroll
        for (int i = 0; i < 4; i++)
#pragma unroll
            for (int j = 0; j < 4; j++) s[i][j] = 0.f;

#pragma unroll 4
        for (int d0 = 0; d0 < HD; d0 += 4) {
            float4 qv[4], kv[4];
#pragma unroll
            for (int i = 0; i < 4; i++) qv[i] = *(const float4*)&sQ[(r0 + i) * 64 + d0];
#pragma unroll
            for (int j = 0; j < 4; j++) kv[j] = *(const float4*)&sK[(tc + 16 * j) * KPAD + d0];
#pragma unroll
            for (int i = 0; i < 4; i++)
#pragma unroll
                for (int j = 0; j < 4; j++)
                    s[i][j] += qv[i].x * kv[j].x + qv[i].y * kv[j].y
                             + qv[i].z * kv[j].z + qv[i].w * kv[j].w;
        }

        // Online softmax update
        bool diag = (kt == qt);
#pragma unroll
        for (int i = 0; i < 4; i++) {
#pragma unroll
            for (int j = 0; j < 4; j++) {
                s[i][j] *= 0.125f;   // 1/sqrt(64)
                if (diag && (tc + 16 * j) > (r0 + i)) s[i][j] = -1e30f;
            }
            float rm = fmaxf(fmaxf(s[i][0], s[i][1]), fmaxf(s[i][2], s[i][3]));
            rm = fmaxf(rm, __shfl_xor_sync(0xffffffffu, rm, 1));
            rm = fmaxf(rm, __shfl_xor_sync(0xffffffffu, rm, 2));
            rm = fmaxf(rm, __shfl_xor_sync(0xffffffffu, rm, 4));
            rm = fmaxf(rm, __shfl_xor_sync(0xffffffffu, rm, 8));
            float mn = fmaxf(m[i], rm);
            float alpha = __expf(m[i] - mn);
            m[i] = mn;
            float rs = 0.f;
#pragma unroll
            for (int j = 0; j < 4; j++) {
                float p = __expf(s[i][j] - mn);
                sP[(r0 + i) * KPAD + tc + 16 * j] = p;
                rs += p;
            }
            rs += __shfl_xor_sync(0xffffffffu, rs, 1);
            rs += __shfl_xor_sync(0xffffffffu, rs, 2);
            rs += __shfl_xor_sync(0xffffffffu, rs, 4);
            rs += __shfl_xor_sync(0xffffffffu, rs, 8);
            l[i] = l[i] * alpha + rs;
#pragma unroll
            for (int j = 0; j < 4; j++) acc[i][j] *= alpha;
        }
        __syncthreads();  // sP visible to all

        // O += P @ V : O cols tc*4..tc*4+3
#pragma unroll 8
        for (int c = 0; c < 64; c++) {
            float4 vv = *(const float4*)&sV[c * KPAD + tc * 4];
#pragma unroll
            for (int i = 0; i < 4; i++) {
                float p = sP[(r0 + i) * KPAD + c];
                acc[i][0] += p * vv.x;
                acc[i][1] += p * vv.y;
                acc[i][2] += p * vv.z;
                acc[i][3] += p * vv.w;
            }
        }
    }

    // Normalize and write to [B,T,C] layout for the output projection
    int b = bh >> 4, h = bh & 15;
#pragma unroll
    for (int i = 0; i < 4; i++) {
        float inv = 1.0f / l[i];
        int trow = qt * 64 + r0 + i;
        float4 o;
        o.x = acc[i][0] * inv;
        o.y = acc[i][1] * inv;
        o.z = acc[i][2] * inv;
        o.w = acc[i][3] * inv;
        *(float4*)&g_att[((size_t)(b * TT + trow)) * CC + h * HD + tc * 4] = o;
    }
}

// ---------------------------------------------------------------------------
extern "C" void kernel_launch(void* const* d_in, const int* in_sizes, int n_in,
                              void* d_out, int out_size)
{
    const float* x     = (const float*)d_in[0];
    const float* W_qkv = (const float*)d_in[1];
    const float* b_qkv = (const float*)d_in[2];
    const float* W_out = (const float*)d_in[3];
    const float* b_out = (const float*)d_in[4];
    float* out = (float*)d_out;

    float *qkv, *att;
    cudaGetSymbolAddress((void**)&qkv, g_qkv);
    cudaGetSymbolAddress((void**)&att, g_att);

    cudaFuncSetAttribute(flash_attn_kernel,
                         cudaFuncAttributeMaxDynamicSharedMemorySize,
                         ATTN_SMEM_BYTES);

    // 1) QKV projection: [8192,1024] @ [1024,3072] + bias
    sgemm_bias_kernel<<<dim3(NQKV / 128, MM / 128), 256>>>(x, W_qkv, b_qkv, qkv, NQKV, CC);

    // 2) RoPE + head split
    rope_split_kernel<<<(BB * HH * TT * 32) / 256, 256>>>();

    // 3) Causal flash attention
    flash_attn_kernel<<<dim3(TT / 64, BB * HH), 256, ATTN_SMEM_BYTES>>>();

    // 4) Output projection: [8192,1024] @ [1024,1024] + bias
    sgemm_bias_kernel<<<dim3(CC / 128, MM / 128), 256>>>(att, W_out, b_out, out, CC, CC);
}

// round 5
// speedup vs baseline: 1.1068x; 1.1068x over previous
#include <cuda_runtime.h>
#include <math.h>
#include <stdint.h>

#define BB 4
#define TT 2048
#define CC 1024
#define HH 16
#define HD 64
#define MM (BB*TT)          // 8192 rows
#define NQKV (3*CC)         // 3072

// Scratch (device globals; allocation-free per harness rules)
__device__ float g_qkv[(size_t)MM * NQKV];   // [B,T,3C]
__device__ float g_q[(size_t)MM * CC];       // [B,H,T,hd]
__device__ float g_k[(size_t)MM * CC];       // [B,H,T,hd]
__device__ float g_v[(size_t)MM * CC];       // [B,H,T,hd]
__device__ float g_att[(size_t)MM * CC];     // [B,T,C]
__device__ float g_wqkvT[(size_t)NQKV * CC]; // W_qkv^T [3072][1024], tf32-rounded
__device__ float g_woutT[(size_t)CC * CC];   // W_out^T [1024][1024], tf32-rounded

// ---------------------------------------------------------------------------
// Helpers
// ---------------------------------------------------------------------------
__device__ __forceinline__ float cvt_tf32(float x) {
    uint32_t r;
    asm("cvt.rna.tf32.f32 %0, %1;" : "=r"(r) : "f"(x));
    return __uint_as_float(r);
}

#define LDSM_X4(r0, r1, r2, r3, addr)                                         \
    asm volatile("ldmatrix.sync.aligned.m8n8.x4.shared.b16 {%0,%1,%2,%3}, [%4];" \
                 : "=r"(r0), "=r"(r1), "=r"(r2), "=r"(r3) : "r"(addr))

#define MMA_TF32(d, a, b)                                                     \
    asm volatile("mma.sync.aligned.m16n8k8.row.col.f32.tf32.tf32.f32 "        \
                 "{%0,%1,%2,%3}, {%4,%5,%6,%7}, {%8,%9}, {%0,%1,%2,%3};"      \
                 : "+f"(d[0]), "+f"(d[1]), "+f"(d[2]), "+f"(d[3])             \
                 : "r"(a[0]), "r"(a[1]), "r"(a[2]), "r"(a[3]),                \
                   "r"(b[0]), "r"(b[1]))

// ---------------------------------------------------------------------------
// Transpose weights [K][N] -> [N][K] with tf32 rounding (once per launch).
// Block 256 threads handles a 32x32 tile.
// ---------------------------------------------------------------------------
__global__ __launch_bounds__(256) void transpose_tf32_kernel(
    const float* __restrict__ W, float* __restrict__ Wt, int K, int N)
{
    __shared__ float tile[32][33];
    int n0 = blockIdx.x * 32, k0 = blockIdx.y * 32;
    int tx = threadIdx.x & 31, ty = threadIdx.x >> 5;   // 32 x 8
#pragma unroll
    for (int i = 0; i < 32; i += 8)
        tile[ty + i][tx] = W[(size_t)(k0 + ty + i) * N + n0 + tx];
    __syncthreads();
#pragma unroll
    for (int i = 0; i < 32; i += 8)
        Wt[(size_t)(n0 + ty + i) * K + k0 + tx] = cvt_tf32(tile[tx][ty + i]);
}

// ---------------------------------------------------------------------------
// TF32 tensor-core GEMM: C[M,N] = A[M,K] @ Bt[N,K]^T + bias[N]
// A fp32 (rounded to tf32 while staging), Bt already tf32.
// Block tile 128x128x32, 8 warps (4x2), warp tile 32x64 (2 x 8 m16n8k8 frags).
// ---------------------------------------------------------------------------
#define GBM 128
#define GBN 128
#define GBK 32
#define GPAD 36      // 144B row stride: 16B-aligned, LDSM conflict-free

__global__ __launch_bounds__(256, 2) void tf32_gemm_bias(
    const float* __restrict__ A, const float* __restrict__ Bt,
    const float* __restrict__ bias, float* __restrict__ C,
    int Nd, int Kd)
{
    __shared__ float As[GBM * GPAD];
    __shared__ float Bs[GBN * GPAD];

    int tid  = threadIdx.x;
    int warp = tid >> 5, lane = tid & 31;
    int wm   = warp >> 1;                 // 0..3 -> m offset 32*wm
    int wn   = warp & 1;                  // 0..1 -> n offset 64*wn
    int bm   = blockIdx.y * GBM, bn = blockIdx.x * GBN;

    float acc[2][8][4];
#pragma unroll
    for (int mi = 0; mi < 2; mi++)
#pragma unroll
        for (int ni = 0; ni < 8; ni++)
#pragma unroll
            for (int c = 0; c < 4; c++) acc[mi][ni][c] = 0.f;

    // Precompute LDSM lane addresses (row/col offsets within tile).
    int j = lane >> 3;                    // matrix index within x4
    int lrow = lane & 7;
    // A: j -> (rowoff, coloff) = ((j&1)*8, (j>>1)*4)
    int a_row = ((j & 1) << 3) + lrow;
    int a_col = (j >> 1) << 2;
    // B: j -> (rowoff, coloff) = ((j>>1)*8, (j&1)*4)
    int b_row = ((j >> 1) << 3) + lrow;
    int b_col = (j & 1) << 2;

    for (int k0 = 0; k0 < Kd; k0 += GBK) {
        // Stage tiles: 128x32 each, 4 float4 per thread per operand.
#pragma unroll
        for (int it = 0; it < 4; it++) {
            int idx = tid + it * 256;          // 0..1023 float4 slots
            int r = idx >> 3, cq = (idx & 7) << 2;
            float4 a4 = *(const float4*)&A[(size_t)(bm + r) * Kd + k0 + cq];
            a4.x = cvt_tf32(a4.x); a4.y = cvt_tf32(a4.y);
            a4.z = cvt_tf32(a4.z); a4.w = cvt_tf32(a4.w);
            *(float4*)&As[r * GPAD + cq] = a4;
            *(float4*)&Bs[r * GPAD + cq] =
                *(const float4*)&Bt[(size_t)(bn + r) * Kd + k0 + cq];
        }
        __syncthreads();

#pragma unroll
        for (int ks = 0; ks < 4; ks++) {
            int kc = ks * 8;
            uint32_t afr[2][4];
#pragma unroll
            for (int mi = 0; mi < 2; mi++) {
                int mr = wm * 32 + mi * 16;
                uint32_t addr = (uint32_t)__cvta_generic_to_shared(
                    &As[(mr + a_row) * GPAD + kc + a_col]);
                LDSM_X4(afr[mi][0], afr[mi][1], afr[mi][2], afr[mi][3], addr);
            }
            uint32_t bfr[8][2];
#pragma unroll
            for (int np = 0; np < 4; np++) {
                int nb = wn * 64 + np * 16;
                uint32_t addr = (uint32_t)__cvta_generic_to_shared(
                    &Bs[(nb + b_row) * GPAD + kc + b_col]);
                LDSM_X4(bfr[2 * np][0], bfr[2 * np][1],
                        bfr[2 * np + 1][0], bfr[2 * np + 1][1], addr);
            }
#pragma unroll
            for (int mi = 0; mi < 2; mi++)
#pragma unroll
                for (int ni = 0; ni < 8; ni++)
                    MMA_TF32(acc[mi][ni], afr[mi], bfr[ni]);
        }
        __syncthreads();
    }

    // Epilogue: C-frag layout c0:(g, 2q) c1:(g, 2q+1) c2:(g+8, 2q) c3:(g+8, 2q+1)
    int g = lane >> 2, tq = lane & 3;
#pragma unroll
    for (int ni = 0; ni < 8; ni++) {
        int col = bn + wn * 64 + ni * 8 + tq * 2;
        float b0 = bias[col], b1 = bias[col + 1];
#pragma unroll
        for (int mi = 0; mi < 2; mi++) {
            int row = bm + wm * 32 + mi * 16 + g;
            float2 lo = make_float2(acc[mi][ni][0] + b0, acc[mi][ni][1] + b1);
            float2 hi = make_float2(acc[mi][ni][2] + b0, acc[mi][ni][3] + b1);
            *(float2*)&C[(size_t)row * Nd + col]       = lo;
            *(float2*)&C[(size_t)(row + 8) * Nd + col] = hi;
        }
    }
}

// ---------------------------------------------------------------------------
// RoPE + split qkv into head-major Q/K/V layouts [B,H,T,hd].
// ---------------------------------------------------------------------------
__global__ __launch_bounds__(256) void rope_split_kernel()
{
    int idx = blockIdx.x * blockDim.x + threadIdx.x;
    int d = idx & 31;
    int t = (idx >> 5) & (TT - 1);
    int h = (idx >> 16) & (HH - 1);
    int b = idx >> 20;

    const float* row = g_qkv + ((size_t)(b * TT + t)) * NQKV + h * HD + d;
    float q1 = row[0],        q2 = row[32];
    float k1 = row[CC],       k2 = row[CC + 32];
    float v1 = row[2 * CC],   v2 = row[2 * CC + 32];

    float inv = exp2f(-(float)d * 0.4152410118609203f);
    float ang = (float)t * inv;
    float s, c;
    sincosf(ang, &s, &c);

    size_t o = ((size_t)((b * HH + h) * TT + t)) * HD + d;
    g_q[o]      = q1 * c - q2 * s;
    g_q[o + 32] = q2 * c + q1 * s;
    g_k[o]      = k1 * c - k2 * s;
    g_k[o + 32] = k2 * c + k1 * s;
    g_v[o]      = v1;
    g_v[o + 32] = v2;
}

// ---------------------------------------------------------------------------
// Flash attention (fp32, causal). Block = one (b,h) x 64-row Q tile.
// ---------------------------------------------------------------------------
#define KPAD 68
#define ATTN_SMEM_BYTES ((64*64 + 3*64*KPAD) * 4)

__global__ __launch_bounds__(256) void flash_attn_kernel()
{
    extern __shared__ float sm[];
    float* sQ = sm;                       // [64][64]
    float* sK = sm + 64 * 64;             // [64][KPAD]
    float* sV = sK + 64 * KPAD;           // [64][KPAD]
    float* sP = sV + 64 * KPAD;           // [64][KPAD]

    int bh = blockIdx.y;
    int qt = (int)gridDim.x - 1 - (int)blockIdx.x;   // heavy tiles first
    int tid = threadIdx.x;
    int tr = tid >> 4;
    int tc = tid & 15;
    int r0 = tr * 4;

    const float* Qh = g_q + (size_t)bh * TT * HD;
    const float* Kh = g_k + (size_t)bh * TT * HD;
    const float* Vh = g_v + (size_t)bh * TT * HD;

#pragma unroll
    for (int it = 0; it < 4; it++) {
        int i = tid + it * 256;
        int r = i >> 4, dv = (i & 15) << 2;
        *(float4*)&sQ[r * 64 + dv] = *(const float4*)&Qh[(size_t)(qt * 64 + r) * HD + dv];
    }

    float m[4], l[4], acc[4][4];
#pragma unroll
    for (int i = 0; i < 4; i++) {
        m[i] = -1e30f; l[i] = 0.f;
#pragma unroll
        for (int j = 0; j < 4; j++) acc[i][j] = 0.f;
    }

    for (int kt = 0; kt <= qt; kt++) {
        __syncthreads();
#pragma unroll
        for (int it = 0; it < 4; it++) {
            int i = tid + it * 256;
            int r = i >> 4, dv = (i & 15) << 2;
            *(float4*)&sK[r * KPAD + dv] = *(const float4*)&Kh[(size_t)(kt * 64 + r) * HD + dv];
            *(float4*)&sV[r * KPAD + dv] = *(const float4*)&Vh[(size_t)(kt * 64 + r) * HD + dv];
        }
        __syncthreads();

        float s[4][4];
#pragma unroll
        for (int i = 0; i < 4; i++)
#pragma unroll
            for (int j = 0; j < 4; j++) s[i][j] = 0.f;

#pragma unroll 4
        for (int d0 = 0; d0 < HD; d0 += 4) {
            float4 qv[4], kv[4];
#pragma unroll
            for (int i = 0; i < 4; i++) qv[i] = *(const float4*)&sQ[(r0 + i) * 64 + d0];
#pragma unroll
            for (int jj = 0; jj < 4; jj++) kv[jj] = *(const float4*)&sK[(tc + 16 * jj) * KPAD + d0];
#pragma unroll
            for (int i = 0; i < 4; i++)
#pragma unroll
                for (int jj = 0; jj < 4; jj++)
                    s[i][jj] += qv[i].x * kv[jj].x + qv[i].y * kv[jj].y
                              + qv[i].z * kv[jj].z + qv[i].w * kv[jj].w;
        }

        bool diag = (kt == qt);
#pragma unroll
        for (int i = 0; i < 4; i++) {
#pragma unroll
            for (int jj = 0; jj < 4; jj++) {
                s[i][jj] *= 0.125f;
                if (diag && (tc + 16 * jj) > (r0 + i)) s[i][jj] = -1e30f;
            }
            float rm = fmaxf(fmaxf(s[i][0], s[i][1]), fmaxf(s[i][2], s[i][3]));
            rm = fmaxf(rm, __shfl_xor_sync(0xffffffffu, rm, 1));
            rm = fmaxf(rm, __shfl_xor_sync(0xffffffffu, rm, 2));
            rm = fmaxf(rm, __shfl_xor_sync(0xffffffffu, rm, 4));
            rm = fmaxf(rm, __shfl_xor_sync(0xffffffffu, rm, 8));
            float mn = fmaxf(m[i], rm);
            float alpha = __expf(m[i] - mn);
            m[i] = mn;
            float rs = 0.f;
#pragma unroll
            for (int jj = 0; jj < 4; jj++) {
                float p = __expf(s[i][jj] - mn);
                sP[(r0 + i) * KPAD + tc + 16 * jj] = p;
                rs += p;
            }
            rs += __shfl_xor_sync(0xffffffffu, rs, 1);
            rs += __shfl_xor_sync(0xffffffffu, rs, 2);
            rs += __shfl_xor_sync(0xffffffffu, rs, 4);
            rs += __shfl_xor_sync(0xffffffffu, rs, 8);
            l[i] = l[i] * alpha + rs;
#pragma unroll
            for (int jj = 0; jj < 4; jj++) acc[i][jj] *= alpha;
        }
        __syncthreads();

#pragma unroll 8
        for (int c = 0; c < 64; c++) {
            float4 vv = *(const float4*)&sV[c * KPAD + tc * 4];
#pragma unroll
            for (int i = 0; i < 4; i++) {
                float p = sP[(r0 + i) * KPAD + c];
                acc[i][0] += p * vv.x;
                acc[i][1] += p * vv.y;
                acc[i][2] += p * vv.z;
                acc[i][3] += p * vv.w;
            }
        }
    }

    int b = bh >> 4, h = bh & 15;
#pragma unroll
    for (int i = 0; i < 4; i++) {
        float inv = 1.0f / l[i];
        int trow = qt * 64 + r0 + i;
        float4 o;
        o.x = acc[i][0] * inv;
        o.y = acc[i][1] * inv;
        o.z = acc[i][2] * inv;
        o.w = acc[i][3] * inv;
        *(float4*)&g_att[((size_t)(b * TT + trow)) * CC + h * HD + tc * 4] = o;
    }
}

// ---------------------------------------------------------------------------
extern "C" void kernel_launch(void* const* d_in, const int* in_sizes, int n_in,
                              void* d_out, int out_size)
{
    const float* x     = (const float*)d_in[0];
    const float* W_qkv = (const float*)d_in[1];
    const float* b_qkv = (const float*)d_in[2];
    const float* W_out = (const float*)d_in[3];
    const float* b_out = (const float*)d_in[4];
    float* out = (float*)d_out;

    float *qkv, *att, *wqkvT, *woutT;
    cudaGetSymbolAddress((void**)&qkv,   g_qkv);
    cudaGetSymbolAddress((void**)&att,   g_att);
    cudaGetSymbolAddress((void**)&wqkvT, g_wqkvT);
    cudaGetSymbolAddress((void**)&woutT, g_woutT);

    cudaFuncSetAttribute(flash_attn_kernel,
                         cudaFuncAttributeMaxDynamicSharedMemorySize,
                         ATTN_SMEM_BYTES);

    // 0) One-time-per-launch weight transposes (tf32-rounded)
    transpose_tf32_kernel<<<dim3(NQKV / 32, CC / 32), 256>>>(W_qkv, wqkvT, CC, NQKV);
    transpose_tf32_kernel<<<dim3(CC / 32, CC / 32), 256>>>(W_out, woutT, CC, CC);

    // 1) QKV projection: [8192,1024] @ [1024,3072] + bias  (tensor cores)
    tf32_gemm_bias<<<dim3(NQKV / GBN, MM / GBM), 256>>>(x, wqkvT, b_qkv, qkv, NQKV, CC);

    // 2) RoPE + head split
    rope_split_kernel<<<(BB * HH * TT * 32) / 256, 256>>>();

    // 3) Causal flash attention
    flash_attn_kernel<<<dim3(TT / 64, BB * HH), 256, ATTN_SMEM_BYTES>>>();

    // 4) Output projection: [8192,1024] @ [1024,1024] + bias  (tensor cores)
    tf32_gemm_bias<<<dim3(CC / GBN, MM / GBM), 256>>>(att, woutT, b_out, out, CC, CC);
}

// round 6
// speedup vs baseline: 3.4166x; 3.0868x over previous
#include <cuda_runtime.h>
#include <math.h>
#include <stdint.h>

#define BB 4
#define TT 2048
#define CC 1024
#define HH 16
#define HD 64
#define MM (BB*TT)          // 8192 rows
#define NQKV (3*CC)         // 3072

// Scratch (device globals; allocation-free per harness rules)
__device__ float g_xr[(size_t)MM * CC];      // x rounded to tf32
__device__ float g_qkv[(size_t)MM * NQKV];   // [B,T,3C]
__device__ float g_q[(size_t)MM * CC];       // [B,H,T,hd]
__device__ float g_k[(size_t)MM * CC];       // [B,H,T,hd]
__device__ float g_v[(size_t)MM * CC];       // [B,H,T,hd]
__device__ float g_att[(size_t)MM * CC];     // [B,T,C] (tf32-rounded)
__device__ float g_wqkvT[(size_t)NQKV * CC]; // W_qkv^T [3072][1024], tf32
__device__ float g_woutT[(size_t)CC * CC];   // W_out^T [1024][1024], tf32

// ---------------------------------------------------------------------------
// Helpers
// ---------------------------------------------------------------------------
__device__ __forceinline__ float cvt_tf32(float x) {
    uint32_t r;
    asm("cvt.rna.tf32.f32 %0, %1;" : "=r"(r) : "f"(x));
    return __uint_as_float(r);
}

#define LDSM_X4(r0, r1, r2, r3, addr)                                         \
    asm volatile("ldmatrix.sync.aligned.m8n8.x4.shared.b16 {%0,%1,%2,%3}, [%4];" \
                 : "=r"(r0), "=r"(r1), "=r"(r2), "=r"(r3) : "r"(addr))

#define MMA_TF32(d, a, b)                                                     \
    asm volatile("mma.sync.aligned.m16n8k8.row.col.f32.tf32.tf32.f32 "        \
                 "{%0,%1,%2,%3}, {%4,%5,%6,%7}, {%8,%9}, {%0,%1,%2,%3};"      \
                 : "+f"(d[0]), "+f"(d[1]), "+f"(d[2]), "+f"(d[3])             \
                 : "r"(a[0]), "r"(a[1]), "r"(a[2]), "r"(a[3]),                \
                   "r"(b[0]), "r"(b[1]))

#define CP_ASYNC16(dst, src)                                                  \
    asm volatile("cp.async.cg.shared.global [%0], [%1], 16;"                  \
                 :: "r"(dst), "l"(src))
#define CP_COMMIT() asm volatile("cp.async.commit_group;")
#define CP_WAIT(n)  asm volatile("cp.async.wait_group %0;" :: "n"(n))

// ---------------------------------------------------------------------------
// Elementwise tf32 rounding of x (float4 vectorized).
// ---------------------------------------------------------------------------
__global__ __launch_bounds__(256) void round_x_kernel(const float* __restrict__ x)
{
    size_t i = ((size_t)blockIdx.x * 256 + threadIdx.x) * 4;
    float4 v = *(const float4*)&x[i];
    v.x = cvt_tf32(v.x); v.y = cvt_tf32(v.y);
    v.z = cvt_tf32(v.z); v.w = cvt_tf32(v.w);
    *(float4*)&g_xr[i] = v;
}

// ---------------------------------------------------------------------------
// Transpose weights [K][N] -> [N][K] with tf32 rounding (once per launch).
// ---------------------------------------------------------------------------
__global__ __launch_bounds__(256) void transpose_tf32_kernel(
    const float* __restrict__ W, float* __restrict__ Wt, int K, int N)
{
    __shared__ float tile[32][33];
    int n0 = blockIdx.x * 32, k0 = blockIdx.y * 32;
    int tx = threadIdx.x & 31, ty = threadIdx.x >> 5;   // 32 x 8
#pragma unroll
    for (int i = 0; i < 32; i += 8)
        tile[ty + i][tx] = W[(size_t)(k0 + ty + i) * N + n0 + tx];
    __syncthreads();
#pragma unroll
    for (int i = 0; i < 32; i += 8)
        Wt[(size_t)(n0 + ty + i) * K + k0 + tx] = cvt_tf32(tile[tx][ty + i]);
}

// ---------------------------------------------------------------------------
// TF32 tensor-core GEMM, 2-stage cp.async double buffer.
// C[M,N] = A[M,K] @ Bt[N,K]^T + bias[N].  A and Bt pre-rounded to tf32.
// Block tile 128x128x32, 8 warps (4x2), warp tile 32x64.
// ---------------------------------------------------------------------------
#define GBM 128
#define GBN 128
#define GBK 32
#define GPAD 36
#define GEMM_SMEM (2 * (GBM + GBN) * GPAD * 4)

__global__ __launch_bounds__(256, 2) void tf32_gemm_bias(
    const float* __restrict__ A, const float* __restrict__ Bt,
    const float* __restrict__ bias, float* __restrict__ C,
    int Nd, int Kd)
{
    extern __shared__ float smem[];
    float* Asm = smem;                       // [2][GBM*GPAD]
    float* Bsm = smem + 2 * GBM * GPAD;      // [2][GBN*GPAD]

    int tid  = threadIdx.x;
    int warp = tid >> 5, lane = tid & 31;
    int wm   = warp >> 1;
    int wn   = warp & 1;
    int bm   = blockIdx.y * GBM, bn = blockIdx.x * GBN;

    float acc[2][8][4];
#pragma unroll
    for (int mi = 0; mi < 2; mi++)
#pragma unroll
        for (int ni = 0; ni < 8; ni++)
#pragma unroll
            for (int c = 0; c < 4; c++) acc[mi][ni][c] = 0.f;

    int j = lane >> 3;
    int lrow = lane & 7;
    int a_row = ((j & 1) << 3) + lrow;
    int a_col = (j >> 1) << 2;
    int b_row = ((j >> 1) << 3) + lrow;
    int b_col = (j & 1) << 2;

    // Per-thread copy slots: 4 per operand
    int cr = tid >> 3;             // 0..31 base row
    int ccq = (tid & 7) << 2;      // col (float4)

    uint32_t sA[2], sB[2];
#pragma unroll
    for (int bf = 0; bf < 2; bf++) {
        sA[bf] = (uint32_t)__cvta_generic_to_shared(&Asm[bf * GBM * GPAD]);
        sB[bf] = (uint32_t)__cvta_generic_to_shared(&Bsm[bf * GBN * GPAD]);
    }

#define GEMM_ISSUE(buf, k0)                                                   \
    {                                                                         \
        _Pragma("unroll")                                                     \
        for (int it = 0; it < 4; it++) {                                      \
            int r = cr + it * 32;                                             \
            uint32_t da = sA[buf] + (r * GPAD + ccq) * 4;                     \
            const float* pa = &A[(size_t)(bm + r) * Kd + (k0) + ccq];         \
            CP_ASYNC16(da, pa);                                               \
            uint32_t db = sB[buf] + (r * GPAD + ccq) * 4;                     \
            const float* pb = &Bt[(size_t)(bn + r) * Kd + (k0) + ccq];        \
            CP_ASYNC16(db, pb);                                               \
        }                                                                     \
        CP_COMMIT();                                                          \
    }

    int iters = Kd / GBK;
    GEMM_ISSUE(0, 0);

    for (int i = 0; i < iters; i++) {
        if (i + 1 < iters) {
            GEMM_ISSUE((i + 1) & 1, (i + 1) * GBK);
            CP_WAIT(1);
        } else {
            CP_WAIT(0);
        }
        __syncthreads();

        const float* As = &Asm[(i & 1) * GBM * GPAD];
        const float* Bs = &Bsm[(i & 1) * GBN * GPAD];

#pragma unroll
        for (int ks = 0; ks < 4; ks++) {
            int kc = ks * 8;
            uint32_t afr[2][4];
#pragma unroll
            for (int mi = 0; mi < 2; mi++) {
                int mr = wm * 32 + mi * 16;
                uint32_t addr = (uint32_t)__cvta_generic_to_shared(
                    &As[(mr + a_row) * GPAD + kc + a_col]);
                LDSM_X4(afr[mi][0], afr[mi][1], afr[mi][2], afr[mi][3], addr);
            }
            uint32_t bfr[8][2];
#pragma unroll
            for (int np = 0; np < 4; np++) {
                int nb = wn * 64 + np * 16;
                uint32_t addr = (uint32_t)__cvta_generic_to_shared(
                    &Bs[(nb + b_row) * GPAD + kc + b_col]);
                LDSM_X4(bfr[2 * np][0], bfr[2 * np][1],
                        bfr[2 * np + 1][0], bfr[2 * np + 1][1], addr);
            }
#pragma unroll
            for (int mi = 0; mi < 2; mi++)
#pragma unroll
                for (int ni = 0; ni < 8; ni++)
                    MMA_TF32(acc[mi][ni], afr[mi], bfr[ni]);
        }
        __syncthreads();
    }

    int g = lane >> 2, tq = lane & 3;
#pragma unroll
    for (int ni = 0; ni < 8; ni++) {
        int col = bn + wn * 64 + ni * 8 + tq * 2;
        float b0 = bias[col], b1 = bias[col + 1];
#pragma unroll
        for (int mi = 0; mi < 2; mi++) {
            int row = bm + wm * 32 + mi * 16 + g;
            float2 lo = make_float2(acc[mi][ni][0] + b0, acc[mi][ni][1] + b1);
            float2 hi = make_float2(acc[mi][ni][2] + b0, acc[mi][ni][3] + b1);
            *(float2*)&C[(size_t)row * Nd + col]       = lo;
            *(float2*)&C[(size_t)(row + 8) * Nd + col] = hi;
        }
    }
}

// ---------------------------------------------------------------------------
// RoPE + split qkv into head-major Q/K/V layouts [B,H,T,hd].
// ---------------------------------------------------------------------------
__global__ __launch_bounds__(256) void rope_split_kernel()
{
    int idx = blockIdx.x * blockDim.x + threadIdx.x;
    int d = idx & 31;
    int t = (idx >> 5) & (TT - 1);
    int h = (idx >> 16) & (HH - 1);
    int b = idx >> 20;

    const float* row = g_qkv + ((size_t)(b * TT + t)) * NQKV + h * HD + d;
    float q1 = row[0],        q2 = row[32];
    float k1 = row[CC],       k2 = row[CC + 32];
    float v1 = row[2 * CC],   v2 = row[2 * CC + 32];

    float inv = exp2f(-(float)d * 0.4152410118609203f);
    float ang = (float)t * inv;
    float s, c;
    sincosf(ang, &s, &c);

    size_t o = ((size_t)((b * HH + h) * TT + t)) * HD + d;
    g_q[o]      = q1 * c - q2 * s;
    g_q[o + 32] = q2 * c + q1 * s;
    g_k[o]      = k1 * c - k2 * s;
    g_k[o + 32] = k2 * c + k1 * s;
    g_v[o]      = v1;
    g_v[o + 32] = v2;
}

// ---------------------------------------------------------------------------
// Flash attention with TF32 mma.sync.
// CTA = one (b,h) x 128-row Q tile; 8 warps x 16 rows; KV tiles of 64.
// S fragments are reused directly as P A-fragments for P@V by permuting
// V's kv rows (a = {c0,c2,c1,c3}; kv row e -> 2e / 2e+1).
// ---------------------------------------------------------------------------
#define QPAD 68
#define VS 72
#define ATTN_SMEM ((128 * QPAD + 64 * QPAD + 64 * VS) * 4)

__global__ __launch_bounds__(256, 2) void flash_attn_mma()
{
    extern __shared__ float sm[];
    float* sQ  = sm;                     // [128][QPAD]
    float* sK  = sm + 128 * QPAD;        // [64][QPAD]   (rows = kv, cols = hd)
    float* sVt = sK + 64 * QPAD;         // [64 hd][VS]  (swizzled kv columns)

    int bh = blockIdx.y;
    int qt = (int)gridDim.x - 1 - (int)blockIdx.x;   // heavy tiles first
    int tid = threadIdx.x;
    int warp = tid >> 5, lane = tid & 31;
    int g = lane >> 2, q = lane & 3;

    const float* Qh = g_q + (size_t)bh * TT * HD;
    const float* Kh = g_k + (size_t)bh * TT * HD;
    const float* Vh = g_v + (size_t)bh * TT * HD;

    int jm = lane >> 3, lrow = lane & 7;
    int a_row = ((jm & 1) << 3) + lrow, a_col = (jm >> 1) << 2;
    int b_row = ((jm >> 1) << 3) + lrow, b_col = (jm & 1) << 2;

    // Load Q tile (tf32-rounded)
#pragma unroll
    for (int it = 0; it < 8; it++) {
        int idx = tid + it * 256;
        int r = idx >> 4, c4 = (idx & 15) << 2;
        float4 v = *(const float4*)&Qh[(size_t)(qt * 128 + r) * HD + c4];
        v.x = cvt_tf32(v.x); v.y = cvt_tf32(v.y);
        v.z = cvt_tf32(v.z); v.w = cvt_tf32(v.w);
        *(float4*)&sQ[r * QPAD + c4] = v;
    }

    float m0 = -1e30f, m1 = -1e30f, l0 = 0.f, l1 = 0.f;
    float oacc[8][4];
#pragma unroll
    for (int ni = 0; ni < 8; ni++)
#pragma unroll
        for (int c = 0; c < 4; c++) oacc[ni][c] = 0.f;

    int row0 = qt * 128 + warp * 16 + g;
    int row1 = row0 + 8;

    int ktmax = 2 * qt + 1;
    for (int kt = 0; kt <= ktmax; kt++) {
        int kb = kt * 64;
        __syncthreads();
        // Load K tile + V tile (transposed, swizzled), tf32-rounded
#pragma unroll
        for (int it = 0; it < 4; it++) {
            int idx = tid + it * 256;
            int r = idx >> 4, c4 = (idx & 15) << 2;
            float4 kv4 = *(const float4*)&Kh[(size_t)(kb + r) * HD + c4];
            kv4.x = cvt_tf32(kv4.x); kv4.y = cvt_tf32(kv4.y);
            kv4.z = cvt_tf32(kv4.z); kv4.w = cvt_tf32(kv4.w);
            *(float4*)&sK[r * QPAD + c4] = kv4;

            float4 vv4 = *(const float4*)&Vh[(size_t)(kb + r) * HD + c4];
            int sw = (((c4 >> 2) & 3) << 3);
            int rsw = r ^ sw;
            sVt[(c4 + 0) * VS + rsw] = cvt_tf32(vv4.x);
            sVt[(c4 + 1) * VS + rsw] = cvt_tf32(vv4.y);
            sVt[(c4 + 2) * VS + rsw] = cvt_tf32(vv4.z);
            sVt[(c4 + 3) * VS + rsw] = cvt_tf32(vv4.w);
        }
        __syncthreads();

        // S = Q @ K^T (warp: 16 x 64)
        float sf[8][4];
#pragma unroll
        for (int ni = 0; ni < 8; ni++)
#pragma unroll
            for (int c = 0; c < 4; c++) sf[ni][c] = 0.f;

#pragma unroll
        for (int kc8 = 0; kc8 < 8; kc8++) {
            int kc = kc8 * 8;
            uint32_t afr[4];
            uint32_t aad = (uint32_t)__cvta_generic_to_shared(
                &sQ[(warp * 16 + a_row) * QPAD + kc + a_col]);
            LDSM_X4(afr[0], afr[1], afr[2], afr[3], aad);
            uint32_t bfr[8][2];
#pragma unroll
            for (int np = 0; np < 4; np++) {
                uint32_t bad = (uint32_t)__cvta_generic_to_shared(
                    &sK[(np * 16 + b_row) * QPAD + kc + b_col]);
                LDSM_X4(bfr[2 * np][0], bfr[2 * np][1],
                        bfr[2 * np + 1][0], bfr[2 * np + 1][1], bad);
            }
#pragma unroll
            for (int ni = 0; ni < 8; ni++)
                MMA_TF32(sf[ni], afr, bfr[ni]);
        }

        // Online softmax on fragments
        bool maskt = (kt >= 2 * qt);
        float rmax0 = -1e30f, rmax1 = -1e30f;
#pragma unroll
        for (int ni = 0; ni < 8; ni++) {
            sf[ni][0] *= 0.125f; sf[ni][1] *= 0.125f;
            sf[ni][2] *= 0.125f; sf[ni][3] *= 0.125f;
            if (maskt) {
                int c0 = kb + ni * 8 + 2 * q, c1 = c0 + 1;
                if (c0 > row0) sf[ni][0] = -1e30f;
                if (c1 > row0) sf[ni][1] = -1e30f;
                if (c0 > row1) sf[ni][2] = -1e30f;
                if (c1 > row1) sf[ni][3] = -1e30f;
            }
            rmax0 = fmaxf(rmax0, fmaxf(sf[ni][0], sf[ni][1]));
            rmax1 = fmaxf(rmax1, fmaxf(sf[ni][2], sf[ni][3]));
        }
        rmax0 = fmaxf(rmax0, __shfl_xor_sync(0xffffffffu, rmax0, 1));
        rmax0 = fmaxf(rmax0, __shfl_xor_sync(0xffffffffu, rmax0, 2));
        rmax1 = fmaxf(rmax1, __shfl_xor_sync(0xffffffffu, rmax1, 1));
        rmax1 = fmaxf(rmax1, __shfl_xor_sync(0xffffffffu, rmax1, 2));

        float mn0 = fmaxf(m0, rmax0), mn1 = fmaxf(m1, rmax1);
        float al0 = __expf(m0 - mn0), al1 = __expf(m1 - mn1);
        m0 = mn0; m1 = mn1;

        float rs0 = 0.f, rs1 = 0.f;
#pragma unroll
        for (int ni = 0; ni < 8; ni++) {
            float p0 = cvt_tf32(__expf(sf[ni][0] - mn0));
            float p1 = cvt_tf32(__expf(sf[ni][1] - mn0));
            float p2 = cvt_tf32(__expf(sf[ni][2] - mn1));
            float p3 = cvt_tf32(__expf(sf[ni][3] - mn1));
            sf[ni][0] = p0; sf[ni][1] = p1; sf[ni][2] = p2; sf[ni][3] = p3;
            rs0 += p0 + p1;
            rs1 += p2 + p3;
        }
        rs0 += __shfl_xor_sync(0xffffffffu, rs0, 1);
        rs0 += __shfl_xor_sync(0xffffffffu, rs0, 2);
        rs1 += __shfl_xor_sync(0xffffffffu, rs1, 1);
        rs1 += __shfl_xor_sync(0xffffffffu, rs1, 2);
        l0 = l0 * al0 + rs0;
        l1 = l1 * al1 + rs1;
#pragma unroll
        for (int ni = 0; ni < 8; ni++) {
            oacc[ni][0] *= al0; oacc[ni][1] *= al0;
            oacc[ni][2] *= al1; oacc[ni][3] *= al1;
        }

        // O += P @ V   (V rows permuted: effective col e -> kv 2e / 2e+1)
#pragma unroll
        for (int kc8 = 0; kc8 < 8; kc8++) {
            uint32_t a[4];
            a[0] = __float_as_uint(sf[kc8][0]);
            a[1] = __float_as_uint(sf[kc8][2]);
            a[2] = __float_as_uint(sf[kc8][1]);
            a[3] = __float_as_uint(sf[kc8][3]);
            int cbase = kc8 * 8 + 2 * q;
#pragma unroll
            for (int ni = 0; ni < 8; ni++) {
                int n = ni * 8 + g;
                int sw = (((n >> 2) & 3) << 3);
                float2 bv = *(const float2*)&sVt[n * VS + (cbase ^ sw)];
                uint32_t b[2];
                b[0] = __float_as_uint(bv.x);
                b[1] = __float_as_uint(bv.y);
                MMA_TF32(oacc[ni], a, b);
            }
        }
    }

    // Epilogue: normalize, tf32-round (feeds out-proj GEMM), write [B,T,C]
    float inv0 = 1.0f / l0, inv1 = 1.0f / l1;
    int b_ = bh >> 4, h = bh & 15;
    int trow0 = qt * 128 + warp * 16 + g;
#pragma unroll
    for (int ni = 0; ni < 8; ni++) {
        int col = h * HD + ni * 8 + 2 * q;
        float2 lo = make_float2(cvt_tf32(oacc[ni][0] * inv0),
                                cvt_tf32(oacc[ni][1] * inv0));
        float2 hi = make_float2(cvt_tf32(oacc[ni][2] * inv1),
                                cvt_tf32(oacc[ni][3] * inv1));
        *(float2*)&g_att[((size_t)(b_ * TT + trow0)) * CC + col]     = lo;
        *(float2*)&g_att[((size_t)(b_ * TT + trow0 + 8)) * CC + col] = hi;
    }
}

// ---------------------------------------------------------------------------
extern "C" void kernel_launch(void* const* d_in, const int* in_sizes, int n_in,
                              void* d_out, int out_size)
{
    const float* x     = (const float*)d_in[0];
    const float* W_qkv = (const float*)d_in[1];
    const float* b_qkv = (const float*)d_in[2];
    const float* W_out = (const float*)d_in[3];
    const float* b_out = (const float*)d_in[4];
    float* out = (float*)d_out;

    float *xr, *qkv, *att, *wqkvT, *woutT;
    cudaGetSymbolAddress((void**)&xr,    g_xr);
    cudaGetSymbolAddress((void**)&qkv,   g_qkv);
    cudaGetSymbolAddress((void**)&att,   g_att);
    cudaGetSymbolAddress((void**)&wqkvT, g_wqkvT);
    cudaGetSymbolAddress((void**)&woutT, g_woutT);

    cudaFuncSetAttribute(tf32_gemm_bias,
                         cudaFuncAttributeMaxDynamicSharedMemorySize, GEMM_SMEM);
    cudaFuncSetAttribute(flash_attn_mma,
                         cudaFuncAttributeMaxDynamicSharedMemorySize, ATTN_SMEM);

    // 0) Weight transposes (tf32) + x rounding
    transpose_tf32_kernel<<<dim3(NQKV / 32, CC / 32), 256>>>(W_qkv, wqkvT, CC, NQKV);
    transpose_tf32_kernel<<<dim3(CC / 32, CC / 32), 256>>>(W_out, woutT, CC, CC);
    round_x_kernel<<<(MM * CC) / (256 * 4), 256>>>(x);

    // 1) QKV projection (tensor cores, cp.async pipelined)
    tf32_gemm_bias<<<dim3(NQKV / GBN, MM / GBM), 256, GEMM_SMEM>>>(
        xr, wqkvT, b_qkv, qkv, NQKV, CC);

    // 2) RoPE + head split
    rope_split_kernel<<<(BB * HH * TT * 32) / 256, 256>>>();

    // 3) Causal flash attention (tensor cores)
    flash_attn_mma<<<dim3(TT / 128, BB * HH), 256, ATTN_SMEM>>>();

    // 4) Output projection (tensor cores)
    tf32_gemm_bias<<<dim3(CC / GBN, MM / GBM), 256, GEMM_SMEM>>>(
        att, woutT, b_out, out, CC, CC);
}

// round 10
// speedup vs baseline: 3.6729x; 1.0750x over previous
#include <cuda_runtime.h>
#include <math.h>
#include <stdint.h>

#define BB 4
#define TT 2048
#define CC 1024
#define HH 16
#define HD 64
#define MM (BB*TT)          // 8192 rows
#define NQKV (3*CC)         // 3072

// Scratch (device globals; allocation-free per harness rules)
__device__ float g_xr[(size_t)MM * CC];      // x rounded to tf32
__device__ float g_q[(size_t)MM * CC];       // [B,H,T,hd] tf32
__device__ float g_k[(size_t)MM * CC];       // [B,H,T,hd] tf32
__device__ float g_v[(size_t)MM * CC];       // [B,H,T,hd] tf32
__device__ float g_att[(size_t)MM * CC];     // [B,T,C] tf32
__device__ float g_wqkvT[(size_t)NQKV * CC]; // W_qkv^T [3072][1024], tf32
__device__ float g_woutT[(size_t)CC * CC];   // W_out^T [1024][1024], tf32

// ---------------------------------------------------------------------------
// Helpers
// ---------------------------------------------------------------------------
__device__ __forceinline__ float cvt_tf32(float x) {
    uint32_t r;
    asm("cvt.rna.tf32.f32 %0, %1;" : "=r"(r) : "f"(x));
    return __uint_as_float(r);
}

#define LDSM_X4(r0, r1, r2, r3, addr)                                         \
    asm volatile("ldmatrix.sync.aligned.m8n8.x4.shared.b16 {%0,%1,%2,%3}, [%4];" \
                 : "=r"(r0), "=r"(r1), "=r"(r2), "=r"(r3) : "r"(addr))

#define MMA_TF32(d, a, b)                                                     \
    asm volatile("mma.sync.aligned.m16n8k8.row.col.f32.tf32.tf32.f32 "        \
                 "{%0,%1,%2,%3}, {%4,%5,%6,%7}, {%8,%9}, {%0,%1,%2,%3};"      \
                 : "+f"(d[0]), "+f"(d[1]), "+f"(d[2]), "+f"(d[3])             \
                 : "r"(a[0]), "r"(a[1]), "r"(a[2]), "r"(a[3]),                \
                   "r"(b[0]), "r"(b[1]))

#define CP_ASYNC16(dst, src)                                                  \
    asm volatile("cp.async.cg.shared.global [%0], [%1], 16;"                  \
                 :: "r"(dst), "l"(src))
#define CP_COMMIT() asm volatile("cp.async.commit_group;")
#define CP_WAIT(n)  asm volatile("cp.async.wait_group %0;" :: "n"(n))

// ---------------------------------------------------------------------------
// Elementwise tf32 rounding of x.
// ---------------------------------------------------------------------------
__global__ __launch_bounds__(256) void round_x_kernel(const float* __restrict__ x)
{
    size_t i = ((size_t)blockIdx.x * 256 + threadIdx.x) * 4;
    float4 v = *(const float4*)&x[i];
    v.x = cvt_tf32(v.x); v.y = cvt_tf32(v.y);
    v.z = cvt_tf32(v.z); v.w = cvt_tf32(v.w);
    *(float4*)&g_xr[i] = v;
}

// ---------------------------------------------------------------------------
// Transpose weights [K][N] -> [N][K] with tf32 rounding.
// ---------------------------------------------------------------------------
__global__ __launch_bounds__(256) void transpose_tf32_kernel(
    const float* __restrict__ W, float* __restrict__ Wt, int K, int N)
{
    __shared__ float tile[32][33];
    int n0 = blockIdx.x * 32, k0 = blockIdx.y * 32;
    int tx = threadIdx.x & 31, ty = threadIdx.x >> 5;
#pragma unroll
    for (int i = 0; i < 32; i += 8)
        tile[ty + i][tx] = W[(size_t)(k0 + ty + i) * N + n0 + tx];
    __syncthreads();
#pragma unroll
    for (int i = 0; i < 32; i += 8)
        Wt[(size_t)(n0 + ty + i) * K + k0 + tx] = cvt_tf32(tile[tx][ty + i]);
}

// ---------------------------------------------------------------------------
// TF32 tensor-core GEMM, 2-stage cp.async double buffer (R6-proven core).
// ROPE=0: C[M,N] = A @ Bt^T + bias  (plain, used for out projection)
// ROPE=1: QKV projection: epilogue applies bias + RoPE + head split, writing
//         tf32-rounded g_q/g_k/g_v in [B,H,T,hd]; C unused.
// ---------------------------------------------------------------------------
#define GBM 128
#define GBN 128
#define GBK 32
#define GPAD 36
#define GEMM_SMEM (2 * (GBM + GBN) * GPAD * 4)

template <int ROPE>
__global__ __launch_bounds__(256, 2) void tf32_gemm(
    const float* __restrict__ A, const float* __restrict__ Bt,
    const float* __restrict__ bias, float* __restrict__ C,
    int Nd, int Kd)
{
    extern __shared__ float smem[];
    float* Asm = smem;                       // [2][GBM*GPAD]
    float* Bsm = smem + 2 * GBM * GPAD;      // [2][GBN*GPAD]

    int tid  = threadIdx.x;
    int warp = tid >> 5, lane = tid & 31;
    int wm   = warp >> 1;
    int wn   = warp & 1;
    int bm   = blockIdx.y * GBM, bn = blockIdx.x * GBN;

    float acc[2][8][4];
#pragma unroll
    for (int mi = 0; mi < 2; mi++)
#pragma unroll
        for (int ni = 0; ni < 8; ni++)
#pragma unroll
            for (int c = 0; c < 4; c++) acc[mi][ni][c] = 0.f;

    int j = lane >> 3;
    int lrow = lane & 7;
    int a_row = ((j & 1) << 3) + lrow;
    int a_col = (j >> 1) << 2;
    int b_row = ((j >> 1) << 3) + lrow;
    int b_col = (j & 1) << 2;

    int cr = tid >> 3;             // 0..31 base row
    int ccq = (tid & 7) << 2;      // col (float4)

    uint32_t sA[2], sB[2];
#pragma unroll
    for (int bf = 0; bf < 2; bf++) {
        sA[bf] = (uint32_t)__cvta_generic_to_shared(&Asm[bf * GBM * GPAD]);
        sB[bf] = (uint32_t)__cvta_generic_to_shared(&Bsm[bf * GBN * GPAD]);
    }

#define GEMM_ISSUE(buf, k0)                                                   \
    {                                                                         \
        _Pragma("unroll")                                                     \
        for (int it = 0; it < 4; it++) {                                      \
            int r = cr + it * 32;                                             \
            uint32_t da = sA[buf] + (r * GPAD + ccq) * 4;                     \
            const float* pa = &A[(size_t)(bm + r) * Kd + (k0) + ccq];         \
            CP_ASYNC16(da, pa);                                               \
            uint32_t db = sB[buf] + (r * GPAD + ccq) * 4;                     \
            const float* pb = &Bt[(size_t)(bn + r) * Kd + (k0) + ccq];        \
            CP_ASYNC16(db, pb);                                               \
        }                                                                     \
        CP_COMMIT();                                                          \
    }

    int iters = Kd / GBK;
    GEMM_ISSUE(0, 0);

    for (int i = 0; i < iters; i++) {
        if (i + 1 < iters) {
            GEMM_ISSUE((i + 1) & 1, (i + 1) * GBK);
            CP_WAIT(1);
        } else {
            CP_WAIT(0);
        }
        __syncthreads();

        const float* As = &Asm[(i & 1) * GBM * GPAD];
        const float* Bs = &Bsm[(i & 1) * GBN * GPAD];

#pragma unroll
        for (int ks = 0; ks < 4; ks++) {
            int kc = ks * 8;
            uint32_t afr[2][4];
#pragma unroll
            for (int mi = 0; mi < 2; mi++) {
                int mr = wm * 32 + mi * 16;
                uint32_t addr = (uint32_t)__cvta_generic_to_shared(
                    &As[(mr + a_row) * GPAD + kc + a_col]);
                LDSM_X4(afr[mi][0], afr[mi][1], afr[mi][2], afr[mi][3], addr);
            }
            uint32_t bfr[8][2];
#pragma unroll
            for (int np = 0; np < 4; np++) {
                int nb = wn * 64 + np * 16;
                uint32_t addr = (uint32_t)__cvta_generic_to_shared(
                    &Bs[(nb + b_row) * GPAD + kc + b_col]);
                LDSM_X4(bfr[2 * np][0], bfr[2 * np][1],
                        bfr[2 * np + 1][0], bfr[2 * np + 1][1], addr);
            }
#pragma unroll
            for (int mi = 0; mi < 2; mi++)
#pragma unroll
                for (int ni = 0; ni < 8; ni++)
                    MMA_TF32(acc[mi][ni], afr[mi], bfr[ni]);
        }
        __syncthreads();
    }

    int g = lane >> 2, tq = lane & 3;

    if (ROPE) {
        // Epilogue: bias + RoPE + head split, write [B,H,T,hd] tf32.
        int n64 = bn + wn * 64;          // this warp's 64-col block
        int sel = n64 >> 10;             // 0=q, 1=k, 2=v
        int h   = (n64 >> 6) & (HH - 1);
        float* dst = (sel == 0) ? g_q : (sel == 1) ? g_k : g_v;

        if (sel == 2) {
#pragma unroll
            for (int mi = 0; mi < 2; mi++) {
#pragma unroll
                for (int half = 0; half < 2; half++) {
                    int row = bm + wm * 32 + mi * 16 + g + half * 8;
                    int t = row & (TT - 1), b = row >> 11;
                    float* o = dst + ((size_t)((b * HH + h) * TT + t)) * HD;
#pragma unroll
                    for (int ni = 0; ni < 8; ni++) {
                        int dl = ni * 8 + tq * 2;
                        float2 val;
                        val.x = cvt_tf32(acc[mi][ni][half * 2]     + bias[n64 + dl]);
                        val.y = cvt_tf32(acc[mi][ni][half * 2 + 1] + bias[n64 + dl + 1]);
                        *(float2*)&o[dl] = val;
                    }
                }
            }
        } else {
            float invf[8];
#pragma unroll
            for (int ni = 0; ni < 4; ni++)
#pragma unroll
                for (int c = 0; c < 2; c++)
                    invf[ni * 2 + c] =
                        exp2f(-(float)(ni * 8 + tq * 2 + c) * 0.4152410118609203f);
#pragma unroll
            for (int mi = 0; mi < 2; mi++) {
#pragma unroll
                for (int half = 0; half < 2; half++) {
                    int row = bm + wm * 32 + mi * 16 + g + half * 8;
                    int t = row & (TT - 1), b = row >> 11;
                    float* o = dst + ((size_t)((b * HH + h) * TT + t)) * HD;
                    float tf = (float)t;
#pragma unroll
                    for (int ni = 0; ni < 4; ni++) {
#pragma unroll
                        for (int c = 0; c < 2; c++) {
                            int dl = ni * 8 + tq * 2 + c;
                            float v1 = acc[mi][ni][half * 2 + c]     + bias[n64 + dl];
                            float v2 = acc[mi][ni + 4][half * 2 + c] + bias[n64 + dl + 32];
                            float s, cs;
                            sincosf(tf * invf[ni * 2 + c], &s, &cs);
                            o[dl]      = cvt_tf32(v1 * cs - v2 * s);
                            o[dl + 32] = cvt_tf32(v2 * cs + v1 * s);
                        }
                    }
                }
            }
        }
    } else {
#pragma unroll
        for (int ni = 0; ni < 8; ni++) {
            int col = bn + wn * 64 + ni * 8 + tq * 2;
            float b0 = bias[col], b1 = bias[col + 1];
#pragma unroll
            for (int mi = 0; mi < 2; mi++) {
                int row = bm + wm * 32 + mi * 16 + g;
                float2 lo = make_float2(acc[mi][ni][0] + b0, acc[mi][ni][1] + b1);
                float2 hi = make_float2(acc[mi][ni][2] + b0, acc[mi][ni][3] + b1);
                *(float2*)&C[(size_t)row * Nd + col]       = lo;
                *(float2*)&C[(size_t)(row + 8) * Nd + col] = hi;
            }
        }
    }
}

// ---------------------------------------------------------------------------
// Flash attention with TF32 mma.sync + 2-stage cp.async K/V pipeline.
// CTA = one (b,h) x 128-row Q tile; 8 warps x 16 rows; KV tiles of 64.
// V kept row-major; P@V B-fragment = two conflict-free LDS.32.
// Q/K/V pre-rounded to tf32 by the QKV GEMM rope epilogue.
// ---------------------------------------------------------------------------
#define AP 68
#define ATTN_SMEM ((128 * AP + 4 * 64 * AP) * 4)

__global__ __launch_bounds__(256, 2) void flash_attn_mma()
{
    extern __shared__ float sm[];
    float* sQ = sm;                      // [128][AP]
    float* sK = sm + 128 * AP;           // [2][64][AP]
    float* sV = sK + 2 * 64 * AP;        // [2][64][AP]

    int bh = blockIdx.y;
    int qt = (int)gridDim.x - 1 - (int)blockIdx.x;   // heavy tiles first
    int tid = threadIdx.x;
    int warp = tid >> 5, lane = tid & 31;
    int g = lane >> 2, q = lane & 3;

    const float* Qh = g_q + (size_t)bh * TT * HD;
    const float* Kh = g_k + (size_t)bh * TT * HD;
    const float* Vh = g_v + (size_t)bh * TT * HD;

    uint32_t uQ = (uint32_t)__cvta_generic_to_shared(sQ);
    uint32_t uK = (uint32_t)__cvta_generic_to_shared(sK);
    uint32_t uV = (uint32_t)__cvta_generic_to_shared(sV);

    int jm = lane >> 3, lrow = lane & 7;
    int a_row = ((jm & 1) << 3) + lrow, a_col = (jm >> 1) << 2;
    int b_row = ((jm >> 1) << 3) + lrow, b_col = (jm & 1) << 2;

    // Prologue: Q (128 rows x 16 chunks = 2048) + KV stage 0 (1024 each).
#pragma unroll
    for (int it = 0; it < 8; it++) {
        int slot = tid + it * 256;
        int r = slot >> 4, c4 = (slot & 15) << 2;
        CP_ASYNC16(uQ + (r * AP + c4) * 4,
                   &Qh[(size_t)(qt * 128 + r) * HD + c4]);
    }
#pragma unroll
    for (int it = 0; it < 4; it++) {
        int slot = tid + it * 256;
        int r = slot >> 4, c4 = (slot & 15) << 2;
        CP_ASYNC16(uK + (r * AP + c4) * 4, &Kh[(size_t)r * HD + c4]);
        CP_ASYNC16(uV + (r * AP + c4) * 4, &Vh[(size_t)r * HD + c4]);
    }
    CP_COMMIT();

    float m0 = -1e30f, m1 = -1e30f, l0 = 0.f, l1 = 0.f;
    float oacc[8][4];
#pragma unroll
    for (int ni = 0; ni < 8; ni++)
#pragma unroll
        for (int c = 0; c < 4; c++) oacc[ni][c] = 0.f;

    int row0 = qt * 128 + warp * 16 + g;
    int row1 = row0 + 8;

    int ktmax = 2 * qt + 1;
    for (int kt = 0; kt <= ktmax; kt++) {
        if (kt > 0) __syncthreads();   // readers of the stage we overwrite are done
        if (kt < ktmax) {
            int ns = (kt + 1) & 1;
            int kb2 = (kt + 1) * 64;
            uint32_t base = (uint32_t)(ns * 64 * AP) * 4;
#pragma unroll
            for (int it = 0; it < 4; it++) {
                int slot = tid + it * 256;
                int r = slot >> 4, c4 = (slot & 15) << 2;
                CP_ASYNC16(uK + base + (r * AP + c4) * 4,
                           &Kh[(size_t)(kb2 + r) * HD + c4]);
                CP_ASYNC16(uV + base + (r * AP + c4) * 4,
                           &Vh[(size_t)(kb2 + r) * HD + c4]);
            }
            CP_COMMIT();
            CP_WAIT(1);
        } else {
            CP_WAIT(0);
        }
        __syncthreads();

        int s = kt & 1;
        int kb = kt * 64;
        const float* sKs = sK + s * 64 * AP;
        const float* sVs = sV + s * 64 * AP;

        // S = Q @ K^T (warp: 16 x 64)
        float sf[8][4];
#pragma unroll
        for (int ni = 0; ni < 8; ni++)
#pragma unroll
            for (int c = 0; c < 4; c++) sf[ni][c] = 0.f;

#pragma unroll
        for (int kc8 = 0; kc8 < 8; kc8++) {
            int kc = kc8 * 8;
            uint32_t afr[4];
            uint32_t aad = (uint32_t)__cvta_generic_to_shared(
                &sQ[(warp * 16 + a_row) * AP + kc + a_col]);
            LDSM_X4(afr[0], afr[1], afr[2], afr[3], aad);
            uint32_t bfr[8][2];
#pragma unroll
            for (int np = 0; np < 4; np++) {
                uint32_t bad = (uint32_t)__cvta_generic_to_shared(
                    &sKs[(np * 16 + b_row) * AP + kc + b_col]);
                LDSM_X4(bfr[2 * np][0], bfr[2 * np][1],
                        bfr[2 * np + 1][0], bfr[2 * np + 1][1], bad);
            }
#pragma unroll
            for (int ni = 0; ni < 8; ni++)
                MMA_TF32(sf[ni], afr, bfr[ni]);
        }

        // Online softmax on fragments
        bool maskt = (kt >= 2 * qt);
        float rmax0 = -1e30f, rmax1 = -1e30f;
#pragma unroll
        for (int ni = 0; ni < 8; ni++) {
            sf[ni][0] *= 0.125f; sf[ni][1] *= 0.125f;
            sf[ni][2] *= 0.125f; sf[ni][3] *= 0.125f;
            if (maskt) {
                int c0 = kb + ni * 8 + 2 * q, c1 = c0 + 1;
                if (c0 > row0) sf[ni][0] = -1e30f;
                if (c1 > row0) sf[ni][1] = -1e30f;
                if (c0 > row1) sf[ni][2] = -1e30f;
                if (c1 > row1) sf[ni][3] = -1e30f;
            }
            rmax0 = fmaxf(rmax0, fmaxf(sf[ni][0], sf[ni][1]));
            rmax1 = fmaxf(rmax1, fmaxf(sf[ni][2], sf[ni][3]));
        }
        rmax0 = fmaxf(rmax0, __shfl_xor_sync(0xffffffffu, rmax0, 1));
        rmax0 = fmaxf(rmax0, __shfl_xor_sync(0xffffffffu, rmax0, 2));
        rmax1 = fmaxf(rmax1, __shfl_xor_sync(0xffffffffu, rmax1, 1));
        rmax1 = fmaxf(rmax1, __shfl_xor_sync(0xffffffffu, rmax1, 2));

        float mn0 = fmaxf(m0, rmax0), mn1 = fmaxf(m1, rmax1);
        float al0 = __expf(m0 - mn0), al1 = __expf(m1 - mn1);
        m0 = mn0; m1 = mn1;

        float rs0 = 0.f, rs1 = 0.f;
#pragma unroll
        for (int ni = 0; ni < 8; ni++) {
            float p0 = cvt_tf32(__expf(sf[ni][0] - mn0));
            float p1 = cvt_tf32(__expf(sf[ni][1] - mn0));
            float p2 = cvt_tf32(__expf(sf[ni][2] - mn1));
            float p3 = cvt_tf32(__expf(sf[ni][3] - mn1));
            sf[ni][0] = p0; sf[ni][1] = p1; sf[ni][2] = p2; sf[ni][3] = p3;
            rs0 += p0 + p1;
            rs1 += p2 + p3;
        }
        rs0 += __shfl_xor_sync(0xffffffffu, rs0, 1);
        rs0 += __shfl_xor_sync(0xffffffffu, rs0, 2);
        rs1 += __shfl_xor_sync(0xffffffffu, rs1, 1);
        rs1 += __shfl_xor_sync(0xffffffffu, rs1, 2);
        l0 = l0 * al0 + rs0;
        l1 = l1 * al1 + rs1;
#pragma unroll
        for (int ni = 0; ni < 8; ni++) {
            oacc[ni][0] *= al0; oacc[ni][1] *= al0;
            oacc[ni][2] *= al1; oacc[ni][3] *= al1;
        }

        // O += P @ V (V row-major; B-frag = two LDS.32, conflict-free)
#pragma unroll
        for (int kc8 = 0; kc8 < 8; kc8++) {
            uint32_t a[4];
            a[0] = __float_as_uint(sf[kc8][0]);
            a[1] = __float_as_uint(sf[kc8][2]);
            a[2] = __float_as_uint(sf[kc8][1]);
            a[3] = __float_as_uint(sf[kc8][3]);
            int cb = kc8 * 8 + 2 * q;
            const float* v0 = &sVs[cb * AP];
            const float* v1 = &sVs[(cb + 1) * AP];
#pragma unroll
            for (int ni = 0; ni < 8; ni++) {
                int n = ni * 8 + g;
                uint32_t b[2];
                b[0] = __float_as_uint(v0[n]);
                b[1] = __float_as_uint(v1[n]);
                MMA_TF32(oacc[ni], a, b);
            }
        }
    }

    // Epilogue: normalize, tf32-round (feeds out-proj GEMM), write [B,T,C]
    float inv0 = 1.0f / l0, inv1 = 1.0f / l1;
    int b_ = bh >> 4, h = bh & 15;
    int trow0 = qt * 128 + warp * 16 + g;
#pragma unroll
    for (int ni = 0; ni < 8; ni++) {
        int col = h * HD + ni * 8 + 2 * q;
        float2 lo = make_float2(cvt_tf32(oacc[ni][0] * inv0),
                                cvt_tf32(oacc[ni][1] * inv0));
        float2 hi = make_float2(cvt_tf32(oacc[ni][2] * inv1),
                                cvt_tf32(oacc[ni][3] * inv1));
        *(float2*)&g_att[((size_t)(b_ * TT + trow0)) * CC + col]     = lo;
        *(float2*)&g_att[((size_t)(b_ * TT + trow0 + 8)) * CC + col] = hi;
    }
}

// ---------------------------------------------------------------------------
extern "C" void kernel_launch(void* const* d_in, const int* in_sizes, int n_in,
                              void* d_out, int out_size)
{
    const float* x     = (const float*)d_in[0];
    const float* W_qkv = (const float*)d_in[1];
    const float* b_qkv = (const float*)d_in[2];
    const float* W_out = (const float*)d_in[3];
    const float* b_out = (const float*)d_in[4];
    float* out = (float*)d_out;

    float *xr, *att, *wqkvT, *woutT;
    cudaGetSymbolAddress((void**)&xr,    g_xr);
    cudaGetSymbolAddress((void**)&att,   g_att);
    cudaGetSymbolAddress((void**)&wqkvT, g_wqkvT);
    cudaGetSymbolAddress((void**)&woutT, g_woutT);

    cudaFuncSetAttribute(tf32_gemm<0>,
                         cudaFuncAttributeMaxDynamicSharedMemorySize, GEMM_SMEM);
    cudaFuncSetAttribute(tf32_gemm<1>,
                         cudaFuncAttributeMaxDynamicSharedMemorySize, GEMM_SMEM);
    cudaFuncSetAttribute(flash_attn_mma,
                         cudaFuncAttributeMaxDynamicSharedMemorySize, ATTN_SMEM);

    // 0) Weight transposes (tf32) + x rounding
    transpose_tf32_kernel<<<dim3(NQKV / 32, CC / 32), 256>>>(W_qkv, wqkvT, CC, NQKV);
    transpose_tf32_kernel<<<dim3(CC / 32, CC / 32), 256>>>(W_out, woutT, CC, CC);
    round_x_kernel<<<(MM * CC) / (256 * 4), 256>>>(x);

    // 1) QKV projection + fused bias/RoPE/head-split epilogue
    tf32_gemm<1><<<dim3(NQKV / GBN, MM / GBM), 256, GEMM_SMEM>>>(
        xr, wqkvT, b_qkv, nullptr, NQKV, CC);

    // 2) Causal flash attention (pipelined K/V)
    flash_attn_mma<<<dim3(TT / 128, BB * HH), 256, ATTN_SMEM>>>();

    // 3) Output projection
    tf32_gemm<0><<<dim3(CC / GBN, MM / GBM), 256, GEMM_SMEM>>>(
        att, woutT, b_out, out, CC, CC);
}